// round 6
// baseline (speedup 1.0000x reference)
#include <cuda_runtime.h>
#include <cuda_fp16.h>
#include <math.h>

#define H_DIM   4096
#define BATCH   64
#define T_STEPS 128
#define I_DIM   1024
#define NNZ_IH  131072
#define NNZ_HH  262144

#define ROWS_PER_BLK 8
#define NB (H_DIM / ROWS_PER_BLK)   // 512 persistent blocks

// ---------------- scratch (device globals; no runtime allocation) ----------------
__device__ __half g_x16[(size_t)T_STEPS * I_DIM * BATCH];  // x as (T, I, B) fp16
__device__ __half g_h16[2][H_DIM * BATCH];                 // h ping-pong (H, B) fp16
__device__ int    g_ih_ptr[H_DIM + 1];
__device__ int    g_hh_ptr[H_DIM + 1];
__device__ int2   g_ih_pk[NNZ_IH];     // (col, val fp32 bits)
__device__ int2   g_hh_pk[NNZ_HH];
__device__ int    g_cnt[2 * H_DIM];
__device__ unsigned g_barCnt;
__device__ unsigned g_barGen;

// ---------------- setup kernels ----------------
__global__ void k_zero_all() {
    int idx = blockIdx.x * blockDim.x + threadIdx.x;
    if (idx < H_DIM * BATCH) g_h16[0][idx] = __float2half(0.0f);
    if (idx < 2 * H_DIM)     g_cnt[idx]   = 0;
    if (idx == 0) { g_barCnt = 0; g_barGen = 0; }
}

__global__ void k_zero_cnt() {
    int idx = blockIdx.x * blockDim.x + threadIdx.x;
    if (idx < 2 * H_DIM) g_cnt[idx] = 0;
}

__global__ void k_hist(const int* __restrict__ ih_rows, const int* __restrict__ hh_rows) {
    int k = blockIdx.x * blockDim.x + threadIdx.x;
    if (k < NNZ_IH) atomicAdd(&g_cnt[ih_rows[k]], 1);
    if (k < NNZ_HH) atomicAdd(&g_cnt[H_DIM + hh_rows[k]], 1);
}

// exclusive scan of 4096 counts -> row pointers (one block per matrix)
__global__ void k_scan() {
    __shared__ int sums[1024];
    int which = blockIdx.x;              // 0 = ih, 1 = hh
    int* cnt = &g_cnt[which * H_DIM];
    int* ptr = which ? g_hh_ptr : g_ih_ptr;
    int tid  = threadIdx.x;
    int base = tid * 4;
    int v0 = cnt[base + 0];
    int v1 = cnt[base + 1];
    int v2 = cnt[base + 2];
    int v3 = cnt[base + 3];
    int local = v0 + v1 + v2 + v3;
    sums[tid] = local;
    __syncthreads();
    for (int off = 1; off < 1024; off <<= 1) {
        int t = (tid >= off) ? sums[tid - off] : 0;
        __syncthreads();
        sums[tid] += t;
        __syncthreads();
    }
    int excl = sums[tid] - local;
    ptr[base + 0] = excl;
    ptr[base + 1] = excl + v0;
    ptr[base + 2] = excl + v0 + v1;
    ptr[base + 3] = excl + v0 + v1 + v2;
    if (tid == 1023) ptr[H_DIM] = sums[1023];
}

__global__ void k_scatter(const int* __restrict__ ih_rows, const int* __restrict__ ih_cols,
                          const float* __restrict__ ih_vals,
                          const int* __restrict__ hh_rows, const int* __restrict__ hh_cols,
                          const float* __restrict__ hh_vals) {
    int k = blockIdx.x * blockDim.x + threadIdx.x;
    if (k < NNZ_IH) {
        int r = ih_rows[k];
        int p = g_ih_ptr[r] + atomicAdd(&g_cnt[r], 1);
        g_ih_pk[p] = make_int2(ih_cols[k], __float_as_int(ih_vals[k]));
    }
    if (k < NNZ_HH) {
        int r = hh_rows[k];
        int p = g_hh_ptr[r] + atomicAdd(&g_cnt[H_DIM + r], 1);
        g_hh_pk[p] = make_int2(hh_cols[k], __float_as_int(hh_vals[k]));
    }
}

// x (B,T,I) fp32 -> g_x16 (T,I,B) fp16
__global__ void k_transpose_x(const float* __restrict__ x) {
    __shared__ float tile[32][33];
    int t  = blockIdx.z;
    int i0 = blockIdx.x * 32;
    int b0 = blockIdx.y * 32;
    int b = b0 + threadIdx.y;
    int i = i0 + threadIdx.x;
    tile[threadIdx.y][threadIdx.x] = x[((size_t)b * T_STEPS + t) * I_DIM + i];
    __syncthreads();
    int iw = i0 + threadIdx.y;
    int bw = b0 + threadIdx.x;
    g_x16[((size_t)t * I_DIM + iw) * BATCH + bw] =
        __float2half(tile[threadIdx.x][threadIdx.y]);
}

// ---------------- persistent RNN kernel ----------------
// 512 blocks, all co-resident (4 blocks/SM enforced via __launch_bounds__).
// warp = 1 row; lane = batch pair. ih gathers overlap the grid barrier.
__global__ void __launch_bounds__(256, 4)
k_rnn(const float* __restrict__ bias, float* __restrict__ out) {
    int lane = threadIdx.x;
    int ty   = threadIdx.y;
    int r    = blockIdx.x * ROWS_PER_BLK + ty;

    // loop-invariant row metadata (L1-resident across all steps)
    float bv  = bias[r];
    int ih0 = g_ih_ptr[r], ih1 = g_ih_ptr[r + 1];
    int hh0 = g_hh_ptr[r], hh1 = g_hh_ptr[r + 1];

    __shared__ float tile[ROWS_PER_BLK][BATCH + 1];

    for (int t = 0; t < T_STEPS; t++) {
        // ---- ih phase: independent of h, runs before the barrier ----
        const __half2* __restrict__ xb =
            (const __half2*)(g_x16 + (size_t)t * I_DIM * BATCH);
        float ax = bv, ay = bv;
        #pragma unroll 4
        for (int k = ih0; k < ih1; k++) {
            int2 w = g_ih_pk[k];
            float v = __int_as_float(w.y);
            float2 f = __half22float2(xb[w.x * (BATCH / 2) + lane]);
            ax += v * f.x;
            ay += v * f.y;
        }

        // ---- grid barrier: h(t-1) writes from all blocks are complete ----
        if (t > 0) {
            __syncthreads();
            if (lane == 0 && ty == 0) {
                __threadfence();
                unsigned arr = atomicAdd(&g_barCnt, 1);
                if (arr == NB - 1) {
                    g_barCnt = 0;
                    __threadfence();
                    atomicAdd(&g_barGen, 1);
                } else {
                    while (*(volatile unsigned*)&g_barGen < (unsigned)t)
                        __nanosleep(64);
                }
            }
            __syncthreads();
        }

        // ---- hh phase: gather h(t-1) via L2 (ldcg — L1 may be stale) ----
        const __half2* __restrict__ hb =
            (const __half2*)g_h16[t & 1];          // h(t-1) lives in buf t&1
        #pragma unroll 4
        for (int k = hh0; k < hh1; k++) {
            int2 w = g_hh_pk[k];
            float v = __int_as_float(w.y);
            float2 f = __half22float2(__ldcg(hb + w.x * (BATCH / 2) + lane));
            ax += v * f.x;
            ay += v * f.y;
        }

        float hx = tanhf(ax);
        float hy = tanhf(ay);

        // h(t) -> buf (t&1)^1, one 128B line per warp
        ((__half2*)g_h16[(t & 1) ^ 1])[r * (BATCH / 2) + lane] =
            __floats2half2_rn(hx, hy);

        // out (B,T,H) fp32 via smem transpose for coalesced stores
        tile[ty][2 * lane]     = hx;
        tile[ty][2 * lane + 1] = hy;
        __syncthreads();
        int idx = ty * 32 + lane;                       // 0..255
        #pragma unroll
        for (int s = 0; s < 2; s++) {
            int id = idx + s * 256;                     // 0..511
            int b  = id >> 3;                           // 0..63
            int rr = id & 7;                            // 0..7
            out[((size_t)b * T_STEPS + t) * H_DIM
                + blockIdx.x * ROWS_PER_BLK + rr] = tile[rr][b];
        }
        // no trailing sync needed: next iter's barrier __syncthreads
        // precedes the next tile write (t=0 path has no prior tile use)
    }
}

// ---------------- launch ----------------
extern "C" void kernel_launch(void* const* d_in, const int* in_sizes, int n_in,
                              void* d_out, int out_size) {
    const float* x       = (const float*)d_in[0];
    const float* ih_vals = (const float*)d_in[1];
    const float* hh_vals = (const float*)d_in[2];
    const float* hh_bias = (const float*)d_in[3];
    const int*   ih_rows = (const int*)  d_in[4];
    const int*   ih_cols = (const int*)  d_in[5];
    const int*   hh_rows = (const int*)  d_in[6];
    const int*   hh_cols = (const int*)  d_in[7];
    float* out = (float*)d_out;

    // CSR build + x transpose/convert (graph-capturable, deterministic)
    k_zero_all<<<(H_DIM * BATCH + 255) / 256, 256>>>();
    k_hist<<<(NNZ_HH + 255) / 256, 256>>>(ih_rows, hh_rows);
    k_scan<<<2, 1024>>>();
    k_zero_cnt<<<(2 * H_DIM + 255) / 256, 256>>>();
    k_scatter<<<(NNZ_HH + 255) / 256, 256>>>(ih_rows, ih_cols, ih_vals,
                                             hh_rows, hh_cols, hh_vals);
    k_transpose_x<<<dim3(I_DIM / 32, BATCH / 32, T_STEPS), dim3(32, 32)>>>(x);

    // one persistent kernel runs all 128 steps
    k_rnn<<<NB, dim3(32, ROWS_PER_BLK)>>>(hh_bias, out);
}

// round 7
// speedup vs baseline: 1.2903x; 1.2903x over previous
#include <cuda_runtime.h>
#include <cuda_fp16.h>
#include <math.h>

#define H_DIM   4096
#define BATCH   64
#define T_STEPS 128
#define I_DIM   1024
#define NNZ_IH  131072
#define NNZ_HH  262144

#define ROWS_PER_BLK 8

// ---------------- scratch (device globals; no runtime allocation) ----------------
__device__ __half g_x16[(size_t)T_STEPS * I_DIM * BATCH];   // x as (T, I, B) fp16
__device__ __half g_pre[(size_t)T_STEPS * H_DIM * BATCH];   // bias + W_ih x_t, fp16 (64MB)
__device__ __half g_h16[2][H_DIM * BATCH];                  // h ping-pong (H, B) fp16
__device__ int    g_ih_ptr[H_DIM + 1];
__device__ int    g_hh_ptr[H_DIM + 1];
__device__ int2   g_ih_pk[NNZ_IH];     // (col, val fp32 bits)
__device__ int2   g_hh_pk[NNZ_HH];
__device__ int    g_cnt[2 * H_DIM];

// ---------------- setup kernels ----------------
__global__ void k_zero_all() {
    int idx = blockIdx.x * blockDim.x + threadIdx.x;
    if (idx < H_DIM * BATCH) g_h16[0][idx] = __float2half(0.0f);
    if (idx < 2 * H_DIM)     g_cnt[idx]   = 0;
}

__global__ void k_zero_cnt() {
    int idx = blockIdx.x * blockDim.x + threadIdx.x;
    if (idx < 2 * H_DIM) g_cnt[idx] = 0;
}

__global__ void k_hist(const int* __restrict__ ih_rows, const int* __restrict__ hh_rows) {
    int k = blockIdx.x * blockDim.x + threadIdx.x;
    if (k < NNZ_IH) atomicAdd(&g_cnt[ih_rows[k]], 1);
    if (k < NNZ_HH) atomicAdd(&g_cnt[H_DIM + hh_rows[k]], 1);
}

// exclusive scan of 4096 counts -> row pointers (one block per matrix)
__global__ void k_scan() {
    __shared__ int sums[1024];
    int which = blockIdx.x;              // 0 = ih, 1 = hh
    int* cnt = &g_cnt[which * H_DIM];
    int* ptr = which ? g_hh_ptr : g_ih_ptr;
    int tid  = threadIdx.x;
    int base = tid * 4;
    int v0 = cnt[base + 0];
    int v1 = cnt[base + 1];
    int v2 = cnt[base + 2];
    int v3 = cnt[base + 3];
    int local = v0 + v1 + v2 + v3;
    sums[tid] = local;
    __syncthreads();
    for (int off = 1; off < 1024; off <<= 1) {
        int t = (tid >= off) ? sums[tid - off] : 0;
        __syncthreads();
        sums[tid] += t;
        __syncthreads();
    }
    int excl = sums[tid] - local;
    ptr[base + 0] = excl;
    ptr[base + 1] = excl + v0;
    ptr[base + 2] = excl + v0 + v1;
    ptr[base + 3] = excl + v0 + v1 + v2;
    if (tid == 1023) ptr[H_DIM] = sums[1023];
}

__global__ void k_scatter(const int* __restrict__ ih_rows, const int* __restrict__ ih_cols,
                          const float* __restrict__ ih_vals,
                          const int* __restrict__ hh_rows, const int* __restrict__ hh_cols,
                          const float* __restrict__ hh_vals) {
    int k = blockIdx.x * blockDim.x + threadIdx.x;
    if (k < NNZ_IH) {
        int r = ih_rows[k];
        int p = g_ih_ptr[r] + atomicAdd(&g_cnt[r], 1);
        g_ih_pk[p] = make_int2(ih_cols[k], __float_as_int(ih_vals[k]));
    }
    if (k < NNZ_HH) {
        int r = hh_rows[k];
        int p = g_hh_ptr[r] + atomicAdd(&g_cnt[H_DIM + r], 1);
        g_hh_pk[p] = make_int2(hh_cols[k], __float_as_int(hh_vals[k]));
    }
}

// x (B,T,I) fp32 -> g_x16 (T,I,B) fp16
__global__ void k_transpose_x(const float* __restrict__ x) {
    __shared__ float tile[32][33];
    int t  = blockIdx.z;
    int i0 = blockIdx.x * 32;
    int b0 = blockIdx.y * 32;
    int b = b0 + threadIdx.y;
    int i = i0 + threadIdx.x;
    tile[threadIdx.y][threadIdx.x] = x[((size_t)b * T_STEPS + t) * I_DIM + i];
    __syncthreads();
    int iw = i0 + threadIdx.y;
    int bw = b0 + threadIdx.x;
    g_x16[((size_t)t * I_DIM + iw) * BATCH + bw] =
        __float2half(tile[threadIdx.x][threadIdx.y]);
}

// ---------------- ih precompute: pre[t] = bias + W_ih x_t, all t in parallel ----------------
// grid (512 rowblocks, 128 t), block (32, 8): warp = one (row, t); fully parallel,
// no recurrence -> runs at the LTS cap.
__global__ void __launch_bounds__(256)
k_preih(const float* __restrict__ bias) {
    int lane = threadIdx.x;
    int ty   = threadIdx.y;
    int r    = blockIdx.x * ROWS_PER_BLK + ty;
    int t    = blockIdx.y;

    const __half2* __restrict__ xb =
        (const __half2*)(g_x16 + (size_t)t * I_DIM * BATCH);

    float bv = bias[r];
    float ax = bv, ay = bv;

    int k0 = g_ih_ptr[r];
    int k1 = g_ih_ptr[r + 1];
    #pragma unroll 4
    for (int k = k0; k < k1; k++) {
        int2 w = g_ih_pk[k];
        float v = __int_as_float(w.y);
        float2 f = __half22float2(xb[w.x * (BATCH / 2) + lane]);
        ax += v * f.x;
        ay += v * f.y;
    }

    ((__half2*)(g_pre + (size_t)t * H_DIM * BATCH))[r * (BATCH / 2) + lane] =
        __floats2half2_rn(ax, ay);
}

// ---------------- per-timestep kernel (hh only) ----------------
// block (32, 16): row handled by a warp PAIR (half = ty>>3) splitting its entry
// range contiguously -> 8192 warps chip-wide keeps the LTS pipe full.
__global__ void __launch_bounds__(512)
k_step(float* __restrict__ out, int t, int prev) {
    int lane = threadIdx.x;
    int ty   = threadIdx.y;            // 0..15
    int ry   = ty & 7;
    int half = ty >> 3;
    int r    = blockIdx.x * ROWS_PER_BLK + ry;

    const __half2* __restrict__ hb = (const __half2*)g_h16[prev];

    int k0 = g_hh_ptr[r];
    int k1 = g_hh_ptr[r + 1];
    int mid = (k0 + k1 + 1) >> 1;
    int ka = half ? mid : k0;
    int kb = half ? k1  : mid;

    float ax = 0.0f, ay = 0.0f;
    #pragma unroll 4
    for (int k = ka; k < kb; k++) {
        int2 w = g_hh_pk[k];
        float v = __int_as_float(w.y);
        float2 f = __half22float2(hb[w.x * (BATCH / 2) + lane]);
        ax += v * f.x;
        ay += v * f.y;
    }

    __shared__ float2 part[ROWS_PER_BLK][32];
    __shared__ float  tile[ROWS_PER_BLK][BATCH + 1];

    if (half == 1) part[ry][lane] = make_float2(ax, ay);
    __syncthreads();

    if (half == 0) {
        float2 p = part[ry][lane];
        float2 pre = __half22float2(
            ((const __half2*)(g_pre + (size_t)t * H_DIM * BATCH))
                [r * (BATCH / 2) + lane]);
        float hx = tanhf(pre.x + ax + p.x);
        float hy = tanhf(pre.y + ay + p.y);

        // h(t) fp16: one 128B line per warp
        ((__half2*)g_h16[prev ^ 1])[r * (BATCH / 2) + lane] =
            __floats2half2_rn(hx, hy);

        tile[ry][2 * lane]     = hx;
        tile[ry][2 * lane + 1] = hy;
    }
    __syncthreads();

    // out (B,T,H) fp32, coalesced: 512 threads cover 512 elements
    int idx = ty * 32 + lane;                       // 0..511
    int b   = idx >> 3;                             // 0..63
    int rr  = idx & 7;                              // 0..7
    out[((size_t)b * T_STEPS + t) * H_DIM + blockIdx.x * ROWS_PER_BLK + rr] =
        tile[rr][b];
}

// ---------------- launch ----------------
extern "C" void kernel_launch(void* const* d_in, const int* in_sizes, int n_in,
                              void* d_out, int out_size) {
    const float* x       = (const float*)d_in[0];
    const float* ih_vals = (const float*)d_in[1];
    const float* hh_vals = (const float*)d_in[2];
    const float* hh_bias = (const float*)d_in[3];
    const int*   ih_rows = (const int*)  d_in[4];
    const int*   ih_cols = (const int*)  d_in[5];
    const int*   hh_rows = (const int*)  d_in[6];
    const int*   hh_cols = (const int*)  d_in[7];
    float* out = (float*)d_out;

    // CSR build + x transpose/convert (graph-capturable, deterministic)
    k_zero_all<<<(H_DIM * BATCH + 255) / 256, 256>>>();
    k_hist<<<(NNZ_HH + 255) / 256, 256>>>(ih_rows, hh_rows);
    k_scan<<<2, 1024>>>();
    k_zero_cnt<<<(2 * H_DIM + 255) / 256, 256>>>();
    k_scatter<<<(NNZ_HH + 255) / 256, 256>>>(ih_rows, ih_cols, ih_vals,
                                             hh_rows, hh_cols, hh_vals);
    k_transpose_x<<<dim3(I_DIM / 32, BATCH / 32, T_STEPS), dim3(32, 32)>>>(x);

    // ih term for all timesteps at once (no recurrence -> full parallelism)
    k_preih<<<dim3(H_DIM / ROWS_PER_BLK, T_STEPS), dim3(32, ROWS_PER_BLK)>>>(hh_bias);

    // sequential recurrence: hh gathers only
    for (int t = 0; t < T_STEPS; t++) {
        k_step<<<H_DIM / ROWS_PER_BLK, dim3(32, 16)>>>(out, t, t & 1);
    }
}